// round 6
// baseline (speedup 1.0000x reference)
#include <cuda_runtime.h>
#include <cstdint>

namespace {
constexpr int B_  = 2;
constexpr int H_  = 8;
constexpr int NQ_ = 2048;
constexpr int NK_ = 2048;
constexpr int D_  = 64;
constexpr int TQ_ = 32;
constexpr int TK_ = 32;
constexpr int NTHREADS = 512;        // 16 warps: warp = (mhalf, head)

// Q/K/V tiles: 32 rows x 512 floats, row stride 516 (pad 4).
//   bank(r,col) = (4r + col) & 31 -> fragment accesses conflict-free, no aliasing.
// S tiles: 8 heads x 32 rows x 32, row stride 36; overlays the K region
//   (K is register-resident after phase-1 fragment loads + barrier).
constexpr int QK_STRIDE = 516;
constexpr int TILE_SZ   = 32 * QK_STRIDE;       // 16512 floats
constexpr int OFF_Q   = 0;
constexpr int OFF_K   = TILE_SZ;                // 16512
constexpr int OFF_V   = 2 * TILE_SZ;            // 33024
constexpr int OFF_S   = OFF_K;                  // S overlays K (9216 <= 16512)
constexpr int S_HSTR  = 32 * 36;                // 1152 floats per head
constexpr int SMEM_FLOATS = 3 * TILE_SZ;        // 49536
constexpr size_t SMEM_BYTES = (size_t)SMEM_FLOATS * sizeof(float);  // 198144
}

__device__ __forceinline__ int qk_addr(int row, int col) { return row * QK_STRIDE + col; }
__device__ __forceinline__ int s_addr (int h, int row, int k) { return h * S_HSTR + row * 36 + k; }

__device__ __forceinline__ uint32_t tf32r(float f) {
    uint32_t r; asm("cvt.rna.tf32.f32 %0, %1;" : "=r"(r) : "f"(f)); return r;
}
__device__ __forceinline__ float tf32f(float f) { return __uint_as_float(tf32r(f)); }
__device__ __forceinline__ float tf32relu(float f) { return __uint_as_float(tf32r(fmaxf(f, 0.f))); }

// D += A(16x8,row) * B(8x8,col)   tf32 inputs, f32 accumulate
__device__ __forceinline__ void mma_tf32(float* d, const uint32_t* a, const uint32_t* b) {
    asm volatile(
        "mma.sync.aligned.m16n8k8.row.col.f32.tf32.tf32.f32 "
        "{%0,%1,%2,%3}, {%4,%5,%6,%7}, {%8,%9}, {%0,%1,%2,%3};"
        : "+f"(d[0]), "+f"(d[1]), "+f"(d[2]), "+f"(d[3])
        : "r"(a[0]), "r"(a[1]), "r"(a[2]), "r"(a[3]), "r"(b[0]), "r"(b[1]));
}

__global__ __launch_bounds__(NTHREADS, 1)
void linattn_mma(const float* __restrict__ Qg, const float* __restrict__ Kg,
                 const float* __restrict__ Vg, const float* __restrict__ Mg,
                 float* __restrict__ Og)
{
    extern __shared__ float sm[];
    float* Qs = sm + OFF_Q;
    float* Ks = sm + OFF_K;
    float* Vs = sm + OFF_V;
    float* Ss = sm + OFF_S;

    const int tid   = threadIdx.x;
    const int warp  = tid >> 5;
    const int lane  = tid & 31;
    const int g     = lane >> 2;        // group id 0..7
    const int c     = lane & 3;         // thread-in-group 0..3
    const int h     = warp & 7;         // head
    const int mh    = warp >> 3;        // m-half: rows [16*mh, 16*mh+16)
    const int b     = blockIdx.y;
    const int q0    = blockIdx.x * TQ_;
    const int hcol  = h * D_;
    const int mrow  = 16 * mh + g;      // this thread's fragment base row

    // Normalize-phase coords (2 (q,k) pairs per thread)
    const int nq0 = tid >> 5;           // 0..15   (j=0: q=nq0; j=1: q=nq0+16)
    const int nk  = tid & 31;

    // ---- Load Q tile (relu + tf32 at store) ----
    #pragma unroll
    for (int i = 0; i < 8; i++) {
        int idx = tid + NTHREADS * i;               // 4096 float4
        int q = idx >> 7, rem = idx & 127;
        int hh = rem >> 4, d4 = rem & 15;
        float4 v = *reinterpret_cast<const float4*>(
            Qg + (((size_t)(b * H_ + hh) * NQ_ + q0 + q) * D_ + d4 * 4));
        float4 t;
        t.x = tf32relu(v.x); t.y = tf32relu(v.y);
        t.z = tf32relu(v.z); t.w = tf32relu(v.w);
        *reinterpret_cast<float4*>(&Qs[qk_addr(q, hh * D_ + d4 * 4)]) = t;
    }

    // Persistent O accumulator fragments for this warp's m-half: [ntile][4]
    float oacc[8][4];
    #pragma unroll
    for (int n = 0; n < 8; n++)
        #pragma unroll
        for (int r = 0; r < 4; r++) oacc[n][r] = 0.f;

    __syncthreads();

    for (int k0 = 0; k0 < NK_; k0 += TK_) {
        // ---- Prefetch mask (latency overlaps K/V loads) ----
        const float* mrow0 = Mg + (size_t)b * NQ_ * NK_ + (size_t)(q0 + nq0) * NK_ + k0 + nk;
        float mv0 = *mrow0;
        float mv1 = *(mrow0 + 16 * (size_t)NK_);

        // ---- Load K (relu+tf32) and V (tf32) tiles ----
        #pragma unroll
        for (int i = 0; i < 8; i++) {
            int idx = tid + NTHREADS * i;
            int k = idx >> 7, rem = idx & 127;
            int hh = rem >> 4, d4 = rem & 15;
            size_t go = ((size_t)(b * H_ + hh) * NK_ + k0 + k) * D_ + d4 * 4;
            float4 kv = *reinterpret_cast<const float4*>(Kg + go);
            float4 vv = *reinterpret_cast<const float4*>(Vg + go);
            float4 tk, tv;
            tk.x = tf32relu(kv.x); tk.y = tf32relu(kv.y);
            tk.z = tf32relu(kv.z); tk.w = tf32relu(kv.w);
            tv.x = tf32f(vv.x);    tv.y = tf32f(vv.y);
            tv.z = tf32f(vv.z);    tv.w = tf32f(vv.w);
            *reinterpret_cast<float4*>(&Ks[qk_addr(k, hh * D_ + d4 * 4)]) = tk;
            *reinterpret_cast<float4*>(&Vs[qk_addr(k, hh * D_ + d4 * 4)]) = tv;
        }
        __syncthreads();

        // ---- Phase 1: S_h[16x32] (this warp's m-half) = Q @ K^T ----
        float sacc[4][4];
        #pragma unroll
        for (int n = 0; n < 4; n++)
            #pragma unroll
            for (int r = 0; r < 4; r++) sacc[n][r] = 0.f;

        #pragma unroll
        for (int t = 0; t < 8; t++) {               // k-dim (d) tiles of 8
            const int colb = hcol + 8 * t + c;
            uint32_t a[4], bb[4][2];
            a[0] = __float_as_uint(Qs[qk_addr(mrow,     colb)]);
            a[1] = __float_as_uint(Qs[qk_addr(mrow + 8, colb)]);
            a[2] = __float_as_uint(Qs[qk_addr(mrow,     colb + 4)]);
            a[3] = __float_as_uint(Qs[qk_addr(mrow + 8, colb + 4)]);
            #pragma unroll
            for (int n = 0; n < 4; n++) {
                bb[n][0] = __float_as_uint(Ks[qk_addr(8 * n + g, colb)]);
                bb[n][1] = __float_as_uint(Ks[qk_addr(8 * n + g, colb + 4)]);
            }
            #pragma unroll
            for (int n = 0; n < 4; n++)
                mma_tf32(sacc[n], a, bb[n]);
        }

        // All warps done reading K before S overwrites the K region.
        __syncthreads();

        // Store S fragments (float2: cols 2c,2c+1 contiguous)
        #pragma unroll
        for (int n = 0; n < 4; n++) {
            *reinterpret_cast<float2*>(&Ss[s_addr(h, mrow,     8 * n + 2 * c)]) =
                make_float2(sacc[n][0], sacc[n][1]);
            *reinterpret_cast<float2*>(&Ss[s_addr(h, mrow + 8, 8 * n + 2 * c)]) =
                make_float2(sacc[n][2], sacc[n][3]);
        }
        __syncthreads();

        // ---- Normalize: P = S * mask / sum_h(S), tf32-rounded at store ----
        #pragma unroll
        for (int j = 0; j < 2; j++) {
            const int q = nq0 + 16 * j;
            const float mval = j ? mv1 : mv0;
            float s[H_], den = 0.f;
            #pragma unroll
            for (int hh = 0; hh < H_; hh++) { s[hh] = Ss[s_addr(hh, q, nk)]; den += s[hh]; }
            const float inv = __fdividef(mval, den);
            #pragma unroll
            for (int hh = 0; hh < H_; hh++)
                Ss[s_addr(hh, q, nk)] = tf32f(s[hh] * inv);
        }
        __syncthreads();

        // ---- Phase 2: O_h[16x64] (this warp's m-half) += P @ V ----
        #pragma unroll
        for (int t = 0; t < 4; t++) {               // k-dim (k-rows) tiles of 8
            uint32_t a[4], bb[8][2];
            a[0] = __float_as_uint(Ss[s_addr(h, mrow,     8 * t + c)]);
            a[1] = __float_as_uint(Ss[s_addr(h, mrow + 8, 8 * t + c)]);
            a[2] = __float_as_uint(Ss[s_addr(h, mrow,     8 * t + c + 4)]);
            a[3] = __float_as_uint(Ss[s_addr(h, mrow + 8, 8 * t + c + 4)]);
            #pragma unroll
            for (int n = 0; n < 8; n++) {
                bb[n][0] = __float_as_uint(Vs[qk_addr(8 * t + c,     hcol + 8 * n + g)]);
                bb[n][1] = __float_as_uint(Vs[qk_addr(8 * t + c + 4, hcol + 8 * n + g)]);
            }
            #pragma unroll
            for (int n = 0; n < 8; n++)
                mma_tf32(oacc[n], a, bb[n]);
        }
        __syncthreads();    // S (=K region) and V reused next iteration
    }

    // ---- Epilogue: out = O + raw query ----
    #pragma unroll
    for (int n = 0; n < 8; n++) {
        const int q1 = q0 + mrow;
        const size_t base = ((size_t)(b * H_ + h) * NQ_ + q1) * D_ + 8 * n + 2 * c;
        const float2 r0 = *reinterpret_cast<const float2*>(Qg + base);
        *reinterpret_cast<float2*>(Og + base) =
            make_float2(oacc[n][0] + r0.x, oacc[n][1] + r0.y);
        const size_t base2 = base + 8 * (size_t)D_;   // row q1+8
        const float2 r1 = *reinterpret_cast<const float2*>(Qg + base2);
        *reinterpret_cast<float2*>(Og + base2) =
            make_float2(oacc[n][2] + r1.x, oacc[n][3] + r1.y);
    }
}

extern "C" void kernel_launch(void* const* d_in, const int* in_sizes, int n_in,
                              void* d_out, int out_size)
{
    (void)in_sizes; (void)n_in; (void)out_size;
    const float* Qg = (const float*)d_in[0];
    const float* Kg = (const float*)d_in[1];
    const float* Vg = (const float*)d_in[2];
    const float* Mg = (const float*)d_in[3];
    float* Og = (float*)d_out;

    static bool attr_set = false;
    if (!attr_set) {
        cudaFuncSetAttribute(linattn_mma,
                             cudaFuncAttributeMaxDynamicSharedMemorySize,
                             (int)SMEM_BYTES);
        attr_set = true;
    }

    dim3 grid(NQ_ / TQ_, B_);   // (64, 2) = 128 CTAs, one wave
    linattn_mma<<<grid, NTHREADS, SMEM_BYTES>>>(Qg, Kg, Vg, Mg, Og);
}

// round 7
// speedup vs baseline: 1.1045x; 1.1045x over previous
#include <cuda_runtime.h>
#include <cstdint>

namespace {
constexpr int B_  = 2;
constexpr int H_  = 8;
constexpr int NQ_ = 2048;
constexpr int NK_ = 2048;
constexpr int D_  = 64;
constexpr int TQ_ = 32;
constexpr int TK_ = 32;
constexpr int ITERS = NK_ / TK_;     // 64
constexpr int NTHREADS = 256;        // 8 warps = 8 heads

// Q tile: 32 x 512, row stride 516 (bank rotation 4): fragment loads conflict-free.
// K tile: same stride, holds RAW fp32 (relu+cvt at fragment load), cp.async target.
// V tile: row stride 520 (rotation 8): phase-2 B-fragment banks (8c+g+8n) -> CF.
// S tile: 8 heads x 32 x 32, row stride 33 (den reads / P writes CF; frag 2-way).
constexpr int QK_STRIDE = 516;
constexpr int V_STRIDE  = 520;
constexpr int S_STRIDE  = 33;
constexpr int OFF_Q = 0;                        // 16512 floats
constexpr int OFF_K = 16512;                    // 16512
constexpr int OFF_V = 33024;                    // 16640
constexpr int OFF_S = 49664;                    // 8448
constexpr int S_HSTR = 32 * S_STRIDE;           // 1056
constexpr int SMEM_FLOATS = OFF_S + H_ * S_HSTR;            // 58112
constexpr size_t SMEM_BYTES = (size_t)SMEM_FLOATS * sizeof(float);  // 232448 = opt-in max
}

__device__ __forceinline__ int qk_addr(int row, int col) { return row * QK_STRIDE + col; }
__device__ __forceinline__ int v_addr (int row, int col) { return row * V_STRIDE  + col; }
__device__ __forceinline__ int s_addr (int h, int row, int k) { return h * S_HSTR + row * S_STRIDE + k; }

__device__ __forceinline__ uint32_t smem_u32(const void* p) {
    uint32_t a;
    asm("{ .reg .u64 t; cvta.to.shared.u64 t, %1; cvt.u32.u64 %0, t; }" : "=r"(a) : "l"(p));
    return a;
}
__device__ __forceinline__ uint32_t tf32r(float f) {
    uint32_t r; asm("cvt.rna.tf32.f32 %0, %1;" : "=r"(r) : "f"(f)); return r;
}
__device__ __forceinline__ float tf32f(float f) { return __uint_as_float(tf32r(f)); }
__device__ __forceinline__ float tf32relu(float f) { return __uint_as_float(tf32r(fmaxf(f, 0.f))); }

__device__ __forceinline__ void cp16(uint32_t dst, const float* src) {
    asm volatile("cp.async.cg.shared.global [%0], [%1], 16;" :: "r"(dst), "l"(src) : "memory");
}
__device__ __forceinline__ void cp_commit() { asm volatile("cp.async.commit_group;" ::: "memory"); }
__device__ __forceinline__ void cp_wait1()  { asm volatile("cp.async.wait_group 1;" ::: "memory"); }

// D += A(16x8,row) * B(8x8,col)   tf32 inputs, f32 accumulate
__device__ __forceinline__ void mma_tf32(float* d, const uint32_t* a, const uint32_t* b) {
    asm volatile(
        "mma.sync.aligned.m16n8k8.row.col.f32.tf32.tf32.f32 "
        "{%0,%1,%2,%3}, {%4,%5,%6,%7}, {%8,%9}, {%0,%1,%2,%3};"
        : "+f"(d[0]), "+f"(d[1]), "+f"(d[2]), "+f"(d[3])
        : "r"(a[0]), "r"(a[1]), "r"(a[2]), "r"(a[3]), "r"(b[0]), "r"(b[1]));
}

__global__ __launch_bounds__(NTHREADS, 1)
void linattn_mma(const float* __restrict__ Qg, const float* __restrict__ Kg,
                 const float* __restrict__ Vg, const float* __restrict__ Mg,
                 float* __restrict__ Og)
{
    extern __shared__ float sm[];
    float* Qs = sm + OFF_Q;
    float* Ks = sm + OFF_K;
    float* Vs = sm + OFF_V;
    float* Ss = sm + OFF_S;
    const uint32_t sb   = smem_u32(sm);
    const uint32_t sb_k = sb + OFF_K * 4u;
    const uint32_t sb_v = sb + OFF_V * 4u;

    const int tid  = threadIdx.x;
    const int warp = tid >> 5;          // warp == head h
    const int lane = tid & 31;
    const int g    = lane >> 2;         // 0..7
    const int c    = lane & 3;          // 0..3
    const int b    = blockIdx.y;
    const int q0   = blockIdx.x * TQ_;
    const int h    = warp;
    const int hcol = h * D_;

    // ---- Load Q tile (relu + tf32 at store) ----
    #pragma unroll
    for (int i = 0; i < 16; i++) {
        int idx = tid + NTHREADS * i;               // 4096 float4
        int q = idx >> 7, rem = idx & 127;
        int hh = rem >> 4, d4 = rem & 15;
        float4 v = *reinterpret_cast<const float4*>(
            Qg + (((size_t)(b * H_ + hh) * NQ_ + q0 + q) * D_ + d4 * 4));
        float4 t;
        t.x = tf32relu(v.x); t.y = tf32relu(v.y);
        t.z = tf32relu(v.z); t.w = tf32relu(v.w);
        *reinterpret_cast<float4*>(&Qs[qk_addr(q, hh * D_ + d4 * 4)]) = t;
    }

    // ---- Prologue: prefetch K(0) then V(0), each its own group ----
    #pragma unroll
    for (int i = 0; i < 16; i++) {
        int idx = tid + NTHREADS * i;
        int k = idx >> 7, rem = idx & 127;
        int hh = rem >> 4, d4 = rem & 15;
        cp16(sb_k + (uint32_t)(qk_addr(k, hh * D_ + d4 * 4)) * 4u,
             Kg + (((size_t)(b * H_ + hh) * NK_ + k) * D_ + d4 * 4));
    }
    cp_commit();
    #pragma unroll
    for (int i = 0; i < 16; i++) {
        int idx = tid + NTHREADS * i;
        int k = idx >> 7, rem = idx & 127;
        int hh = rem >> 4, d4 = rem & 15;
        cp16(sb_v + (uint32_t)(v_addr(k, hh * D_ + d4 * 4)) * 4u,
             Vg + (((size_t)(b * H_ + hh) * NK_ + k) * D_ + d4 * 4));
    }
    cp_commit();

    // Persistent O accumulator fragments: [mtile][ntile][4]
    float oacc[2][8][4];
    #pragma unroll
    for (int m = 0; m < 2; m++)
        #pragma unroll
        for (int n = 0; n < 8; n++)
            #pragma unroll
            for (int r = 0; r < 4; r++) oacc[m][n][r] = 0.f;

    for (int it = 0; it < ITERS; it++) {
        const int k0 = it * TK_;

        // ---- Mask prefetch (hidden under phase 1) ----
        float mv[4];
        #pragma unroll
        for (int j = 0; j < 4; j++) {
            int idx = tid + NTHREADS * j;
            int mq = idx >> 5, mk = idx & 31;
            mv[j] = Mg[(size_t)b * NQ_ * NK_ + (size_t)(q0 + mq) * NK_ + k0 + mk];
        }

        cp_wait1();            // K(it) complete (V(it) may be pending)
        __syncthreads();       // K(it) + Q (it==0) + P region reuse visible

        // ---- Phase 1: S_h[32x32] = relu(Q) @ relu(K)^T (relu+cvt on K frags) ----
        float sacc[2][4][4];
        #pragma unroll
        for (int m = 0; m < 2; m++)
            #pragma unroll
            for (int n = 0; n < 4; n++)
                #pragma unroll
                for (int r = 0; r < 4; r++) sacc[m][n][r] = 0.f;

        #pragma unroll
        for (int t = 0; t < 8; t++) {
            const int colb = hcol + 8 * t + c;
            uint32_t a[2][4], bb[4][2];
            #pragma unroll
            for (int m = 0; m < 2; m++) {
                a[m][0] = __float_as_uint(Qs[qk_addr(16 * m + g,     colb)]);
                a[m][1] = __float_as_uint(Qs[qk_addr(16 * m + g + 8, colb)]);
                a[m][2] = __float_as_uint(Qs[qk_addr(16 * m + g,     colb + 4)]);
                a[m][3] = __float_as_uint(Qs[qk_addr(16 * m + g + 8, colb + 4)]);
            }
            #pragma unroll
            for (int n = 0; n < 4; n++) {
                bb[n][0] = tf32r(fmaxf(Ks[qk_addr(8 * n + g, colb)],     0.f));
                bb[n][1] = tf32r(fmaxf(Ks[qk_addr(8 * n + g, colb + 4)], 0.f));
            }
            #pragma unroll
            for (int m = 0; m < 2; m++)
                #pragma unroll
                for (int n = 0; n < 4; n++)
                    mma_tf32(sacc[m][n], a[m], bb[n]);
        }

        // ---- Store raw S (32-bit stores; stride 33) ----
        #pragma unroll
        for (int m = 0; m < 2; m++)
            #pragma unroll
            for (int n = 0; n < 4; n++) {
                Ss[s_addr(h, 16 * m + g,     8 * n + 2 * c)]     = sacc[m][n][0];
                Ss[s_addr(h, 16 * m + g,     8 * n + 2 * c + 1)] = sacc[m][n][1];
                Ss[s_addr(h, 16 * m + g + 8, 8 * n + 2 * c)]     = sacc[m][n][2];
                Ss[s_addr(h, 16 * m + g + 8, 8 * n + 2 * c + 1)] = sacc[m][n][3];
            }
        __syncthreads();       // all K reads done + S visible

        // ---- Prefetch K(it+1) into the (now free) K buffer ----
        if (it + 1 < ITERS) {
            const int kn = k0 + TK_;
            #pragma unroll
            for (int i = 0; i < 16; i++) {
                int idx = tid + NTHREADS * i;
                int k = idx >> 7, rem = idx & 127;
                int hh = rem >> 4, d4 = rem & 15;
                cp16(sb_k + (uint32_t)(qk_addr(k, hh * D_ + d4 * 4)) * 4u,
                     Kg + (((size_t)(b * H_ + hh) * NK_ + kn + k) * D_ + d4 * 4));
            }
        }
        cp_commit();           // committed even when empty (keeps group count uniform)

        // ---- Normalize in place: P = S * mask / sum_h(S) ----
        #pragma unroll
        for (int j = 0; j < 4; j++) {
            int idx = tid + NTHREADS * j;
            int q = idx >> 5, k = idx & 31;
            float s[H_], den = 0.f;
            #pragma unroll
            for (int hh = 0; hh < H_; hh++) { s[hh] = Ss[s_addr(hh, q, k)]; den += s[hh]; }
            const float inv = __fdividef(mv[j], den);
            #pragma unroll
            for (int hh = 0; hh < H_; hh++)
                Ss[s_addr(hh, q, k)] = tf32f(s[hh] * inv);
        }

        cp_wait1();            // V(it) complete (K(it+1) may be pending)
        __syncthreads();       // P visible + everyone's V(it) done

        // ---- Phase 2: O_h += P_h[32x32] @ V_h[32x64] (cvt on V frags) ----
        #pragma unroll
        for (int t = 0; t < 4; t++) {
            uint32_t a[2][4], bb[8][2];
            #pragma unroll
            for (int m = 0; m < 2; m++) {
                a[m][0] = __float_as_uint(Ss[s_addr(h, 16 * m + g,     8 * t + c)]);
                a[m][1] = __float_as_uint(Ss[s_addr(h, 16 * m + g + 8, 8 * t + c)]);
                a[m][2] = __float_as_uint(Ss[s_addr(h, 16 * m + g,     8 * t + c + 4)]);
                a[m][3] = __float_as_uint(Ss[s_addr(h, 16 * m + g + 8, 8 * t + c + 4)]);
            }
            #pragma unroll
            for (int n = 0; n < 8; n++) {
                bb[n][0] = tf32r(Vs[v_addr(8 * t + c,     hcol + 8 * n + g)]);
                bb[n][1] = tf32r(Vs[v_addr(8 * t + c + 4, hcol + 8 * n + g)]);
            }
            #pragma unroll
            for (int m = 0; m < 2; m++)
                #pragma unroll
                for (int n = 0; n < 8; n++)
                    mma_tf32(oacc[m][n], a[m], bb[n]);
        }
        __syncthreads();       // all V reads done before overwrite

        // ---- Prefetch V(it+1) ----
        if (it + 1 < ITERS) {
            const int kn = k0 + TK_;
            #pragma unroll
            for (int i = 0; i < 16; i++) {
                int idx = tid + NTHREADS * i;
                int k = idx >> 7, rem = idx & 127;
                int hh = rem >> 4, d4 = rem & 15;
                cp16(sb_v + (uint32_t)(v_addr(k, hh * D_ + d4 * 4)) * 4u,
                     Vg + (((size_t)(b * H_ + hh) * NK_ + kn + k) * D_ + d4 * 4));
            }
        }
        cp_commit();
    }

    // ---- Epilogue: out = O + raw query ----
    #pragma unroll
    for (int m = 0; m < 2; m++)
        #pragma unroll
        for (int n = 0; n < 8; n++) {
            const int q1 = q0 + 16 * m + g;
            const size_t base = ((size_t)(b * H_ + h) * NQ_ + q1) * D_ + 8 * n + 2 * c;
            const float2 r0 = *reinterpret_cast<const float2*>(Qg + base);
            *reinterpret_cast<float2*>(Og + base) =
                make_float2(oacc[m][n][0] + r0.x, oacc[m][n][1] + r0.y);
            const size_t base2 = base + 8 * (size_t)D_;   // row q1+8
            const float2 r1 = *reinterpret_cast<const float2*>(Qg + base2);
            *reinterpret_cast<float2*>(Og + base2) =
                make_float2(oacc[m][n][2] + r1.x, oacc[m][n][3] + r1.y);
        }
}

extern "C" void kernel_launch(void* const* d_in, const int* in_sizes, int n_in,
                              void* d_out, int out_size)
{
    (void)in_sizes; (void)n_in; (void)out_size;
    const float* Qg = (const float*)d_in[0];
    const float* Kg = (const float*)d_in[1];
    const float* Vg = (const float*)d_in[2];
    const float* Mg = (const float*)d_in[3];
    float* Og = (float*)d_out;

    static bool attr_set = false;
    if (!attr_set) {
        cudaFuncSetAttribute(linattn_mma,
                             cudaFuncAttributeMaxDynamicSharedMemorySize,
                             (int)SMEM_BYTES);
        attr_set = true;
    }

    dim3 grid(NQ_ / TQ_, B_);   // (64, 2) = 128 CTAs, one wave
    linattn_mma<<<grid, NTHREADS, SMEM_BYTES>>>(Qg, Kg, Vg, Mg, Og);
}